// round 1
// baseline (speedup 1.0000x reference)
#include <cuda_runtime.h>
#include <math.h>

#define NO 512         // objects
#define DD 128         // Din = Dout = H
#define TILE_M 128     // edges per CTA in main kernel

// ---------------- device scratch (static allocation — no cudaMalloc) ----------------
__device__ float g_Wh[NO*DD];
__device__ float g_f1[NO];
__device__ float g_f2[NO];
__device__ float g_hp[NO*DD];
__device__ float g_Hs[NO*DD];   // h' @ W1[0:128,:]   + b1  (source-side table)
__device__ float g_Ho[NO*DD];   // h' @ W1[256:384,:]       (object-side table)
__device__ float g_pooled[NO*DD];
__device__ int   g_cnt[NO];

// ---------------- init: zero accumulators (must run every launch: graph replays) ----
__global__ void k_init() {
    int i = blockIdx.x * blockDim.x + threadIdx.x;
    if (i < NO*DD) g_pooled[i] = 0.f;
    if (i < NO)    g_cnt[i]    = 0;
}

// ---------------- Wh = obj @ W ; f1 = Wh@a1 ; f2 = Wh@a2 ----------------
__global__ void k_wh(const float* __restrict__ obj, const float* __restrict__ W,
                     const float* __restrict__ a) {
    __shared__ float row[DD];
    __shared__ float r1[DD], r2[DD];
    int i = blockIdx.x, k = threadIdx.x;
    row[k] = obj[i*DD + k];
    __syncthreads();
    float s = 0.f;
    #pragma unroll 8
    for (int d = 0; d < DD; d++) s += row[d] * W[d*DD + k];
    g_Wh[i*DD + k] = s;
    r1[k] = s * a[k];
    r2[k] = s * a[DD + k];
    __syncthreads();
    for (int off = 64; off > 0; off >>= 1) {
        if (k < off) { r1[k] += r1[k+off]; r2[k] += r2[k+off]; }
        __syncthreads();
    }
    if (k == 0) { g_f1[i] = r1[0]; g_f2[i] = r2[0]; }
}

// ---------------- attention row softmax + h' = relu(att @ Wh) ----------------
__global__ void k_att() {
    __shared__ float att[NO];
    __shared__ float red[DD];
    int i = blockIdx.x, k = threadIdx.x;
    float f1 = g_f1[i];
    float lmax = -3.0e38f;
    for (int j = k; j < NO; j += DD) {
        float v;
        if (j == i) v = -9.0e15f;                 // masked diagonal
        else { float x = f1 + g_f2[j]; v = (x > 0.f) ? x : 0.2f * x; }  // leaky_relu
        att[j] = v;
        lmax = fmaxf(lmax, v);
    }
    red[k] = lmax; __syncthreads();
    for (int off = 64; off > 0; off >>= 1) { if (k < off) red[k] = fmaxf(red[k], red[k+off]); __syncthreads(); }
    float m = red[0];
    __syncthreads();
    float lsum = 0.f;
    for (int j = k; j < NO; j += DD) { float ev = expf(att[j] - m); att[j] = ev; lsum += ev; }
    red[k] = lsum; __syncthreads();
    for (int off = 64; off > 0; off >>= 1) { if (k < off) red[k] += red[k+off]; __syncthreads(); }
    float inv = 1.f / red[0];
    float acc = 0.f;
    for (int j = 0; j < NO; j++) acc += att[j] * g_Wh[j*DD + k];
    acc *= inv;
    g_hp[i*DD + k] = fmaxf(acc, 0.f);
}

// ---------------- Hs = h'@W1[0:128] + b1 ; Ho = h'@W1[256:384] ----------------
__global__ void k_hsho(const float* __restrict__ W1, const float* __restrict__ b1) {
    __shared__ float h[DD];
    int i = blockIdx.x, k = threadIdx.x;
    h[k] = g_hp[i*DD + k];
    __syncthreads();
    float s1 = b1[k], s2 = 0.f;
    #pragma unroll 4
    for (int d = 0; d < DD; d++) {
        float hv = h[d];
        s1 += hv * W1[d*DD + k];            // rows 0..127   (h'[s] block)
        s2 += hv * W1[(2*DD + d)*DD + k];   // rows 256..383 (h'[o] block)
    }
    g_Hs[i*DD + k] = s1;
    g_Ho[i*DD + k] = s2;
}

// ---------------- edge degree counts ----------------
__global__ void k_counts(const int* __restrict__ edges, int T) {
    __shared__ int h[NO];
    for (int i = threadIdx.x; i < NO; i += blockDim.x) h[i] = 0;
    __syncthreads();
    int stride = gridDim.x * blockDim.x;
    for (int t = blockIdx.x * blockDim.x + threadIdx.x; t < T; t += stride) {
        atomicAdd(&h[edges[2*t]], 1);
        atomicAdd(&h[edges[2*t + 1]], 1);
    }
    __syncthreads();
    for (int i = threadIdx.x; i < NO; i += blockDim.x) if (h[i]) atomicAdd(&g_cnt[i], h[i]);
}

// ---------------- main fused edge-MLP kernel ----------------
// Per CTA: 128 edges.
//  Stage 1: P = pred_tile(128x128) @ W1[128:256,:]   then  h1 = relu(P + Hs[s] + Ho[o])
//  Stage 2: Y = h1 @ W2 chunk-by-chunk (new_p -> out, new_o -> atomics, new_s -> run-reduced atomics)
__global__ __launch_bounds__(256) void k_main(
    const float* __restrict__ pred, const int* __restrict__ edges,
    const float* __restrict__ W1,   const float* __restrict__ W2,
    const float* __restrict__ b2,   float* __restrict__ out_p)
{
    extern __shared__ float sm[];
    float* sHt = sm;                    // 128*132 floats, k-major h1 tile: sHt[c*132 + r]
    float* sA  = sm + 128*132;          // 16*136
    float* sB  = sA + 16*136;           // 16*136
    float* sb2 = sB + 16*136;           // 384
    int*   sS  = (int*)(sb2 + 384);     // 128
    int*   sO  = sS + 128;              // 128

    int tid = threadIdx.x;
    int tx = tid & 15, ty = tid >> 4;   // 16x16 thread grid, each thread 8x8 micro-tile
    int t0 = blockIdx.x * TILE_M;

    if (tid < 128) { sS[tid] = edges[2*(t0 + tid)]; sO[tid] = edges[2*(t0 + tid) + 1]; }
    for (int i = tid; i < 384; i += 256) sb2[i] = b2[i];
    __syncthreads();

    float acc[8][8];
    #pragma unroll
    for (int j = 0; j < 8; j++)
        #pragma unroll
        for (int i2 = 0; i2 < 8; i2++) acc[j][i2] = 0.f;

    // ======== Stage 1 GEMM: P = pred @ W1b ========
    for (int kk = 0; kk < 128; kk += 16) {
        #pragma unroll
        for (int i = tid; i < 2048; i += 256) {
            int r = i >> 4, c = i & 15;
            sA[c*136 + r] = pred[(size_t)(t0 + r) * 128 + kk + c];
        }
        #pragma unroll
        for (int i = tid; i < 2048; i += 256) {
            int c = i >> 7, n = i & 127;
            sB[c*136 + n] = W1[(128 + kk + c) * 128 + n];
        }
        __syncthreads();
        #pragma unroll
        for (int k = 0; k < 16; k++) {
            float4 a0  = *(const float4*)&sA[k*136 + ty*8];
            float4 a1  = *(const float4*)&sA[k*136 + ty*8 + 4];
            float4 b0  = *(const float4*)&sB[k*136 + tx*8];
            float4 b1v = *(const float4*)&sB[k*136 + tx*8 + 4];
            float av[8] = {a0.x,a0.y,a0.z,a0.w,a1.x,a1.y,a1.z,a1.w};
            float bv[8] = {b0.x,b0.y,b0.z,b0.w,b1v.x,b1v.y,b1v.z,b1v.w};
            #pragma unroll
            for (int j = 0; j < 8; j++)
                #pragma unroll
                for (int i2 = 0; i2 < 8; i2++)
                    acc[j][i2] += av[j] * bv[i2];
        }
        __syncthreads();
    }

    // Epilogue 1: h1 = relu(P + Hs[s] + Ho[o]) -> sHt (transposed, k-major)
    #pragma unroll
    for (int j = 0; j < 8; j++) {
        int r = ty*8 + j;
        int sI = sS[r], oI = sO[r];
        const float4* hs = (const float4*)&g_Hs[sI*128 + tx*8];
        const float4* ho = (const float4*)&g_Ho[oI*128 + tx*8];
        float4 h0 = hs[0], h1v = hs[1], q0 = ho[0], q1 = ho[1];
        float add[8] = {h0.x+q0.x, h0.y+q0.y, h0.z+q0.z, h0.w+q0.w,
                        h1v.x+q1.x, h1v.y+q1.y, h1v.z+q1.z, h1v.w+q1.w};
        #pragma unroll
        for (int i2 = 0; i2 < 8; i2++) {
            float v = acc[j][i2] + add[i2];
            sHt[(tx*8 + i2)*132 + r] = fmaxf(v, 0.f);
        }
    }
    __syncthreads();

    // ======== Stage 2: Y = h1 @ W2, chunks in order {new_p, new_o, new_s} ========
    const int order[3] = {1, 2, 0};
    for (int ci = 0; ci < 3; ci++) {
        int ch = order[ci];
        #pragma unroll
        for (int j = 0; j < 8; j++)
            #pragma unroll
            for (int i2 = 0; i2 < 8; i2++) acc[j][i2] = 0.f;

        for (int kk = 0; kk < 128; kk += 16) {
            #pragma unroll
            for (int i = tid; i < 2048; i += 256) {
                int c = i >> 7, n = i & 127;
                sB[c*136 + n] = W2[(kk + c) * 384 + ch*128 + n];
            }
            __syncthreads();
            #pragma unroll
            for (int k = 0; k < 16; k++) {
                float4 a0  = *(const float4*)&sHt[(kk + k)*132 + ty*8];
                float4 a1  = *(const float4*)&sHt[(kk + k)*132 + ty*8 + 4];
                float4 b0  = *(const float4*)&sB[k*136 + tx*8];
                float4 b1v = *(const float4*)&sB[k*136 + tx*8 + 4];
                float av[8] = {a0.x,a0.y,a0.z,a0.w,a1.x,a1.y,a1.z,a1.w};
                float bv[8] = {b0.x,b0.y,b0.z,b0.w,b1v.x,b1v.y,b1v.z,b1v.w};
                #pragma unroll
                for (int j = 0; j < 8; j++)
                    #pragma unroll
                    for (int i2 = 0; i2 < 8; i2++)
                        acc[j][i2] += av[j] * bv[i2];
            }
            __syncthreads();
        }

        if (ch == 1) {
            // new_p -> global output, vectorized
            #pragma unroll
            for (int j = 0; j < 8; j++) {
                int r = ty*8 + j;
                float4 v0, v1;
                v0.x = fmaxf(acc[j][0] + sb2[128 + tx*8 + 0], 0.f);
                v0.y = fmaxf(acc[j][1] + sb2[128 + tx*8 + 1], 0.f);
                v0.z = fmaxf(acc[j][2] + sb2[128 + tx*8 + 2], 0.f);
                v0.w = fmaxf(acc[j][3] + sb2[128 + tx*8 + 3], 0.f);
                v1.x = fmaxf(acc[j][4] + sb2[128 + tx*8 + 4], 0.f);
                v1.y = fmaxf(acc[j][5] + sb2[128 + tx*8 + 5], 0.f);
                v1.z = fmaxf(acc[j][6] + sb2[128 + tx*8 + 6], 0.f);
                v1.w = fmaxf(acc[j][7] + sb2[128 + tx*8 + 7], 0.f);
                *(float4*)&out_p[(size_t)(t0 + r) * 128 + tx*8]     = v0;
                *(float4*)&out_p[(size_t)(t0 + r) * 128 + tx*8 + 4] = v1;
            }
        } else if (ch == 2) {
            // new_o -> atomic scatter (rows within tile hit distinct pooled rows)
            #pragma unroll
            for (int j = 0; j < 8; j++) {
                int r = ty*8 + j;
                int oI = sO[r];
                #pragma unroll
                for (int i2 = 0; i2 < 8; i2++) {
                    float v = fmaxf(acc[j][i2] + sb2[256 + tx*8 + i2], 0.f);
                    atomicAdd(&g_pooled[oI*128 + tx*8 + i2], v);
                }
            }
        } else {
            // new_s: s_idx is sorted (runs of O-1) -> reduce runs in smem, then few atomics.
            // (Correct for any sorted s within tile; our edges enumerate i-major.)
            #pragma unroll
            for (int j = 0; j < 8; j++) {
                int r = ty*8 + j;
                #pragma unroll
                for (int i2 = 0; i2 < 8; i2++)
                    sHt[(tx*8 + i2)*132 + r] = fmaxf(acc[j][i2] + sb2[tx*8 + i2], 0.f);
            }
            __syncthreads();
            if (tid < 128) {
                int c = tid;
                float run = 0.f;
                int cur = sS[0];
                for (int r = 0; r < 128; r++) {
                    int s_ = sS[r];
                    if (s_ != cur) { atomicAdd(&g_pooled[cur*128 + c], run); run = 0.f; cur = s_; }
                    run += sHt[c*132 + r];
                }
                atomicAdd(&g_pooled[cur*128 + c], run);
            }
        }
    }
}

// ---------------- tail: new_obj = mlp2(pooled / counts, W3,b3,W4,b4) ----------------
__global__ void k_tail(const float* __restrict__ W3, const float* __restrict__ b3,
                       const float* __restrict__ W4, const float* __restrict__ b4,
                       float* __restrict__ out_obj) {
    __shared__ float pr[DD];
    __shared__ float hid[2*DD];
    int i = blockIdx.x, k = threadIdx.x;
    float cnt = (float)g_cnt[i];
    if (cnt < 1.f) cnt = 1.f;
    pr[k] = g_pooled[i*DD + k] / cnt;
    __syncthreads();
    for (int n = k; n < 2*DD; n += DD) {
        float s = b3[n];
        #pragma unroll 4
        for (int d = 0; d < DD; d++) s += pr[d] * W3[d*(2*DD) + n];
        hid[n] = fmaxf(s, 0.f);
    }
    __syncthreads();
    float s = b4[k];
    #pragma unroll 4
    for (int d = 0; d < 2*DD; d++) s += hid[d] * W4[d*DD + k];
    out_obj[i*DD + k] = fmaxf(s, 0.f);
}

// ---------------- launch ----------------
extern "C" void kernel_launch(void* const* d_in, const int* in_sizes, int n_in,
                              void* d_out, int out_size) {
    const float* obj   = (const float*)d_in[0];
    const float* pred  = (const float*)d_in[1];
    const int*   edges = (const int*)  d_in[2];
    const float* W     = (const float*)d_in[3];
    const float* a     = (const float*)d_in[4];
    const float* W1    = (const float*)d_in[5];
    const float* b1    = (const float*)d_in[6];
    const float* W2    = (const float*)d_in[7];
    const float* b2    = (const float*)d_in[8];
    const float* W3    = (const float*)d_in[9];
    const float* b3    = (const float*)d_in[10];
    const float* W4    = (const float*)d_in[11];
    const float* b4    = (const float*)d_in[12];

    int T = in_sizes[2] / 2;                 // 261632
    float* out_obj = (float*)d_out;          // (512,128) first
    float* out_p   = (float*)d_out + NO*DD;  // (T,128) second

    size_t smem = (size_t)(128*132 + 2*16*136 + 384) * sizeof(float) + 256 * sizeof(int);
    cudaFuncSetAttribute(k_main, cudaFuncAttributeMaxDynamicSharedMemorySize, (int)smem);

    k_init<<<(NO*DD + 255)/256, 256>>>();
    k_wh<<<NO, DD>>>(obj, W, a);
    k_att<<<NO, DD>>>();
    k_hsho<<<NO, DD>>>(W1, b1);
    k_counts<<<148, 256>>>(edges, T);
    int ntiles = T / TILE_M;                 // 2044 (exact)
    k_main<<<ntiles, 256, smem>>>(pred, edges, W1, W2, b2, out_p);
    k_tail<<<NO, DD>>>(W3, b3, W4, b4, out_obj);
}

// round 3
// speedup vs baseline: 1.0849x; 1.0849x over previous
#include <cuda_runtime.h>
#include <math.h>
#include <stdint.h>

#define NO 512         // objects
#define DD 128         // Din = Dout = H
#define TILE_M 128     // edges per CTA in main kernel
#define LDA 136        // padded smem row stride (floats)

// ---------------- device scratch (static allocation — no cudaMalloc) ----------------
__device__ float g_Wh[NO*DD];
__device__ float g_f1[NO];
__device__ float g_f2[NO];
__device__ float g_hp[NO*DD];
__device__ float g_Hs[NO*DD];   // h' @ W1[0:128,:]   + b1  (source-side table)
__device__ float g_Ho[NO*DD];   // h' @ W1[256:384,:]       (object-side table)
__device__ float g_pooled[NO*DD];
__device__ int   g_cnt[NO];

// ---------------- helpers ----------------
// tf32 round: destination of cvt.rna.tf32.f32 must be a b32 register.
__device__ __forceinline__ float ftf32(float x) {
    uint32_t r; asm("cvt.rna.tf32.f32 %0, %1;" : "=r"(r) : "f"(x));
    return __uint_as_float(r);
}
// permuted column index: within each 8-block, (j, j+4) become adjacent (2j, 2j+1)
__device__ __forceinline__ int pcol(int k) {
    return (k & ~7) | (((k & 3) << 1) | ((k >> 2) & 1));
}
__device__ __forceinline__ void mma_tf32(float* d, uint32_t a0, uint32_t a1, uint32_t a2, uint32_t a3,
                                         uint32_t b0, uint32_t b1) {
    asm volatile(
        "mma.sync.aligned.m16n8k8.row.col.f32.tf32.tf32.f32 "
        "{%0,%1,%2,%3}, {%4,%5,%6,%7}, {%8,%9}, {%0,%1,%2,%3};\n"
        : "+f"(d[0]), "+f"(d[1]), "+f"(d[2]), "+f"(d[3])
        : "r"(a0), "r"(a1), "r"(a2), "r"(a3), "r"(b0), "r"(b1));
}

// ---------------- init: zero accumulators (must run every launch: graph replays) ----
__global__ void k_init() {
    int i = blockIdx.x * blockDim.x + threadIdx.x;
    if (i < NO*DD) g_pooled[i] = 0.f;
    if (i < NO)    g_cnt[i]    = 0;
}

// ---------------- Wh = obj @ W ; f1 = Wh@a1 ; f2 = Wh@a2 ----------------
__global__ void k_wh(const float* __restrict__ obj, const float* __restrict__ W,
                     const float* __restrict__ a) {
    __shared__ float row[DD];
    __shared__ float r1[DD], r2[DD];
    int i = blockIdx.x, k = threadIdx.x;
    row[k] = obj[i*DD + k];
    __syncthreads();
    float s = 0.f;
    #pragma unroll 8
    for (int d = 0; d < DD; d++) s += row[d] * W[d*DD + k];
    g_Wh[i*DD + k] = s;
    r1[k] = s * a[k];
    r2[k] = s * a[DD + k];
    __syncthreads();
    for (int off = 64; off > 0; off >>= 1) {
        if (k < off) { r1[k] += r1[k+off]; r2[k] += r2[k+off]; }
        __syncthreads();
    }
    if (k == 0) { g_f1[i] = r1[0]; g_f2[i] = r2[0]; }
}

// ---------------- attention row softmax + h' = relu(att @ Wh) ----------------
__global__ void k_att() {
    __shared__ float att[NO];
    __shared__ float red[DD];
    int i = blockIdx.x, k = threadIdx.x;
    float f1 = g_f1[i];
    float lmax = -3.0e38f;
    for (int j = k; j < NO; j += DD) {
        float v;
        if (j == i) v = -9.0e15f;
        else { float x = f1 + g_f2[j]; v = (x > 0.f) ? x : 0.2f * x; }
        att[j] = v;
        lmax = fmaxf(lmax, v);
    }
    red[k] = lmax; __syncthreads();
    for (int off = 64; off > 0; off >>= 1) { if (k < off) red[k] = fmaxf(red[k], red[k+off]); __syncthreads(); }
    float m = red[0];
    __syncthreads();
    float lsum = 0.f;
    for (int j = k; j < NO; j += DD) { float ev = expf(att[j] - m); att[j] = ev; lsum += ev; }
    red[k] = lsum; __syncthreads();
    for (int off = 64; off > 0; off >>= 1) { if (k < off) red[k] += red[k+off]; __syncthreads(); }
    float inv = 1.f / red[0];
    float acc = 0.f;
    for (int j = 0; j < NO; j++) acc += att[j] * g_Wh[j*DD + k];
    acc *= inv;
    g_hp[i*DD + k] = fmaxf(acc, 0.f);
}

// ---------------- Hs = h'@W1[0:128] + b1 ; Ho = h'@W1[256:384] ----------------
__global__ void k_hsho(const float* __restrict__ W1, const float* __restrict__ b1) {
    __shared__ float h[DD];
    int i = blockIdx.x, k = threadIdx.x;
    h[k] = g_hp[i*DD + k];
    __syncthreads();
    float s1 = b1[k], s2 = 0.f;
    #pragma unroll 4
    for (int d = 0; d < DD; d++) {
        float hv = h[d];
        s1 += hv * W1[d*DD + k];
        s2 += hv * W1[(2*DD + d)*DD + k];
    }
    g_Hs[i*DD + k] = s1;
    g_Ho[i*DD + k] = s2;
}

// ---------------- edge degree counts ----------------
__global__ void k_counts(const int* __restrict__ edges, int T) {
    __shared__ int h[NO];
    for (int i = threadIdx.x; i < NO; i += blockDim.x) h[i] = 0;
    __syncthreads();
    int stride = gridDim.x * blockDim.x;
    for (int t = blockIdx.x * blockDim.x + threadIdx.x; t < T; t += stride) {
        atomicAdd(&h[edges[2*t]], 1);
        atomicAdd(&h[edges[2*t + 1]], 1);
    }
    __syncthreads();
    for (int i = threadIdx.x; i < NO; i += blockDim.x) if (h[i]) atomicAdd(&g_cnt[i], h[i]);
}

// ---------------- main fused edge-MLP kernel (tf32 tensor cores) ----------------
// 256 threads = 8 warps in a 4(M) x 2(N) grid; warp tile 32x64; mma m16n8k8 tf32.
// Stage 1: P = pred_tile @ W1[128:256,:]; h1 = relu(P + Hs[s] + Ho[o]) -> sA (fragment layout)
// Stage 2: Y = h1 @ W2 per 128-col chunk: {new_p -> out, new_o -> atomics, new_s -> run-reduce}
__global__ __launch_bounds__(256) void k_main(
    const float* __restrict__ pred, const int* __restrict__ edges,
    const float* __restrict__ W1,   const float* __restrict__ W2,
    const float* __restrict__ b2,   float* __restrict__ out_p)
{
    extern __shared__ float smem[];
    float* sA  = smem;                 // 128 x LDA (A tile / h1 tile / new_s scratch)
    float* sB  = smem + 128*LDA;       // 128 x LDA (B tiles, n-major, permuted k)
    float* sb2 = sB + 128*LDA;         // 384
    int*   sS  = (int*)(sb2 + 384);    // 128
    int*   sO  = sS + 128;             // 128

    int tid  = threadIdx.x;
    int wid  = tid >> 5, lane = tid & 31;
    int gid  = lane >> 2, tq = lane & 3;
    int wm   = wid & 3;                // M block: rows wm*32 .. +32
    int wn   = wid >> 2;               // N block: cols wn*64 .. +64
    int t0   = blockIdx.x * TILE_M;

    if (tid < 128) { sS[tid] = edges[2*(t0 + tid)]; sO[tid] = edges[2*(t0 + tid) + 1]; }
    for (int i = tid; i < 384; i += 256) sb2[i] = b2[i];

    // ---- stage A = pred tile (tf32, permuted k cols) ----
    for (int i = tid; i < 128*32; i += 256) {
        int r = i >> 5, c4 = (i & 31) << 2;
        float4 v = *(const float4*)&pred[(size_t)(t0 + r) * 128 + c4];
        float* dst = &sA[r * LDA];
        dst[pcol(c4    )] = ftf32(v.x);
        dst[pcol(c4 + 1)] = ftf32(v.y);
        dst[pcol(c4 + 2)] = ftf32(v.z);
        dst[pcol(c4 + 3)] = ftf32(v.w);
    }
    // ---- stage B = W1[128:256,:] as Bt[n][perm(k)] ----
    for (int i = tid; i < 128*32; i += 256) {
        int k = i >> 5, n4 = (i & 31) << 2;
        float4 v = *(const float4*)&W1[(128 + k) * 128 + n4];
        int pc = pcol(k);
        sB[(n4 + 0)*LDA + pc] = ftf32(v.x);
        sB[(n4 + 1)*LDA + pc] = ftf32(v.y);
        sB[(n4 + 2)*LDA + pc] = ftf32(v.z);
        sB[(n4 + 3)*LDA + pc] = ftf32(v.w);
    }
    __syncthreads();

    float acc[2][8][4];
    #pragma unroll
    for (int mt = 0; mt < 2; mt++)
        #pragma unroll
        for (int nt = 0; nt < 8; nt++)
            #pragma unroll
            for (int q = 0; q < 4; q++) acc[mt][nt][q] = 0.f;

    // ======== GEMM 1 ========
    #pragma unroll 4
    for (int ks = 0; ks < 16; ks++) {
        int kb = ks*8 + 2*tq;
        uint32_t a0[2], a1[2], a2[2], a3[2];
        #pragma unroll
        for (int mt = 0; mt < 2; mt++) {
            int r = wm*32 + mt*16 + gid;
            float2 p0 = *(const float2*)&sA[r*LDA + kb];
            float2 p1 = *(const float2*)&sA[(r + 8)*LDA + kb];
            a0[mt] = __float_as_uint(p0.x); a2[mt] = __float_as_uint(p0.y);
            a1[mt] = __float_as_uint(p1.x); a3[mt] = __float_as_uint(p1.y);
        }
        #pragma unroll
        for (int nt = 0; nt < 8; nt++) {
            int n = wn*64 + nt*8 + gid;
            float2 q = *(const float2*)&sB[n*LDA + kb];
            uint32_t b0 = __float_as_uint(q.x), b1 = __float_as_uint(q.y);
            #pragma unroll
            for (int mt = 0; mt < 2; mt++)
                mma_tf32(acc[mt][nt], a0[mt], a1[mt], a2[mt], a3[mt], b0, b1);
        }
    }
    __syncthreads();

    // ---- epilogue 1: h1 = relu(P + Hs[s] + Ho[o]) -> sA, fragment layout ----
    #pragma unroll
    for (int mt = 0; mt < 2; mt++) {
        int r0 = wm*32 + mt*16 + gid, r1 = r0 + 8;
        int sI0 = sS[r0], oI0 = sO[r0], sI1 = sS[r1], oI1 = sO[r1];
        #pragma unroll
        for (int nt = 0; nt < 8; nt++) {
            int c = wn*64 + nt*8 + 2*tq;
            float2 hs0 = *(const float2*)&g_Hs[sI0*128 + c];
            float2 ho0 = *(const float2*)&g_Ho[oI0*128 + c];
            float2 hs1 = *(const float2*)&g_Hs[sI1*128 + c];
            float2 ho1 = *(const float2*)&g_Ho[oI1*128 + c];
            float v00 = fmaxf(acc[mt][nt][0] + hs0.x + ho0.x, 0.f);
            float v01 = fmaxf(acc[mt][nt][1] + hs0.y + ho0.y, 0.f);
            float v10 = fmaxf(acc[mt][nt][2] + hs1.x + ho1.x, 0.f);
            float v11 = fmaxf(acc[mt][nt][3] + hs1.y + ho1.y, 0.f);
            int pc0 = pcol(c), pc1 = pcol(c + 1);
            sA[r0*LDA + pc0] = ftf32(v00);
            sA[r0*LDA + pc1] = ftf32(v01);
            sA[r1*LDA + pc0] = ftf32(v10);
            sA[r1*LDA + pc1] = ftf32(v11);
        }
    }

    // ======== GEMM 2: 3 chunks of W2, order {new_p, new_o, new_s} ========
    const int order[3] = {1, 2, 0};
    for (int ci = 0; ci < 3; ci++) {
        int ch = order[ci];
        // stage B = W2[:, ch*128 : ch*128+128]
        __syncthreads();   // h1 writes (ci==0) / prior mma reads of sB done
        for (int i = tid; i < 128*32; i += 256) {
            int k = i >> 5, n4 = (i & 31) << 2;
            float4 v = *(const float4*)&W2[k*384 + ch*128 + n4];
            int pc = pcol(k);
            sB[(n4 + 0)*LDA + pc] = ftf32(v.x);
            sB[(n4 + 1)*LDA + pc] = ftf32(v.y);
            sB[(n4 + 2)*LDA + pc] = ftf32(v.z);
            sB[(n4 + 3)*LDA + pc] = ftf32(v.w);
        }
        __syncthreads();

        #pragma unroll
        for (int mt = 0; mt < 2; mt++)
            #pragma unroll
            for (int nt = 0; nt < 8; nt++)
                #pragma unroll
                for (int q = 0; q < 4; q++) acc[mt][nt][q] = 0.f;

        #pragma unroll 4
        for (int ks = 0; ks < 16; ks++) {
            int kb = ks*8 + 2*tq;
            uint32_t a0[2], a1[2], a2[2], a3[2];
            #pragma unroll
            for (int mt = 0; mt < 2; mt++) {
                int r = wm*32 + mt*16 + gid;
                float2 p0 = *(const float2*)&sA[r*LDA + kb];
                float2 p1 = *(const float2*)&sA[(r + 8)*LDA + kb];
                a0[mt] = __float_as_uint(p0.x); a2[mt] = __float_as_uint(p0.y);
                a1[mt] = __float_as_uint(p1.x); a3[mt] = __float_as_uint(p1.y);
            }
            #pragma unroll
            for (int nt = 0; nt < 8; nt++) {
                int n = wn*64 + nt*8 + gid;
                float2 q = *(const float2*)&sB[n*LDA + kb];
                uint32_t b0 = __float_as_uint(q.x), b1 = __float_as_uint(q.y);
                #pragma unroll
                for (int mt = 0; mt < 2; mt++)
                    mma_tf32(acc[mt][nt], a0[mt], a1[mt], a2[mt], a3[mt], b0, b1);
            }
        }

        if (ch == 1) {
            // new_p -> global output (float2 per row-pair)
            #pragma unroll
            for (int mt = 0; mt < 2; mt++) {
                int r0 = wm*32 + mt*16 + gid, r1 = r0 + 8;
                #pragma unroll
                for (int nt = 0; nt < 8; nt++) {
                    int c = wn*64 + nt*8 + 2*tq;
                    float bz0 = sb2[128 + c], bz1 = sb2[128 + c + 1];
                    float2 v0, v1;
                    v0.x = fmaxf(acc[mt][nt][0] + bz0, 0.f);
                    v0.y = fmaxf(acc[mt][nt][1] + bz1, 0.f);
                    v1.x = fmaxf(acc[mt][nt][2] + bz0, 0.f);
                    v1.y = fmaxf(acc[mt][nt][3] + bz1, 0.f);
                    *(float2*)&out_p[(size_t)(t0 + r0) * 128 + c] = v0;
                    *(float2*)&out_p[(size_t)(t0 + r1) * 128 + c] = v1;
                }
            }
        } else if (ch == 2) {
            // new_o -> atomic scatter (distinct rows within tile)
            #pragma unroll
            for (int mt = 0; mt < 2; mt++) {
                int r0 = wm*32 + mt*16 + gid, r1 = r0 + 8;
                int oI0 = sO[r0], oI1 = sO[r1];
                #pragma unroll
                for (int nt = 0; nt < 8; nt++) {
                    int c = wn*64 + nt*8 + 2*tq;
                    float bz0 = sb2[256 + c], bz1 = sb2[256 + c + 1];
                    atomicAdd(&g_pooled[oI0*128 + c],     fmaxf(acc[mt][nt][0] + bz0, 0.f));
                    atomicAdd(&g_pooled[oI0*128 + c + 1], fmaxf(acc[mt][nt][1] + bz1, 0.f));
                    atomicAdd(&g_pooled[oI1*128 + c],     fmaxf(acc[mt][nt][2] + bz0, 0.f));
                    atomicAdd(&g_pooled[oI1*128 + c + 1], fmaxf(acc[mt][nt][3] + bz1, 0.f));
                }
            }
        } else {
            // new_s: s sorted within tile -> run-reduce in smem, few atomics
            __syncthreads();   // all mma reads of sA (h1) complete before overwrite
            #pragma unroll
            for (int mt = 0; mt < 2; mt++) {
                int r0 = wm*32 + mt*16 + gid, r1 = r0 + 8;
                #pragma unroll
                for (int nt = 0; nt < 8; nt++) {
                    int c = wn*64 + nt*8 + 2*tq;
                    float bz0 = sb2[c], bz1 = sb2[c + 1];
                    sA[c*LDA + r0]       = fmaxf(acc[mt][nt][0] + bz0, 0.f);
                    sA[(c + 1)*LDA + r0] = fmaxf(acc[mt][nt][1] + bz1, 0.f);
                    sA[c*LDA + r1]       = fmaxf(acc[mt][nt][2] + bz0, 0.f);
                    sA[(c + 1)*LDA + r1] = fmaxf(acc[mt][nt][3] + bz1, 0.f);
                }
            }
            __syncthreads();
            if (tid < 128) {
                int c = tid;
                float run = 0.f;
                int cur = sS[0];
                for (int r = 0; r < 128; r++) {
                    int s_ = sS[r];
                    if (s_ != cur) { atomicAdd(&g_pooled[cur*128 + c], run); run = 0.f; cur = s_; }
                    run += sA[c*LDA + r];
                }
                atomicAdd(&g_pooled[cur*128 + c], run);
            }
        }
    }
}

// ---------------- tail: new_obj = mlp2(pooled / counts, W3,b3,W4,b4) ----------------
__global__ void k_tail(const float* __restrict__ W3, const float* __restrict__ b3,
                       const float* __restrict__ W4, const float* __restrict__ b4,
                       float* __restrict__ out_obj) {
    __shared__ float pr[DD];
    __shared__ float hid[2*DD];
    int i = blockIdx.x, k = threadIdx.x;
    float cnt = (float)g_cnt[i];
    if (cnt < 1.f) cnt = 1.f;
    pr[k] = g_pooled[i*DD + k] / cnt;
    __syncthreads();
    for (int n = k; n < 2*DD; n += DD) {
        float s = b3[n];
        #pragma unroll 4
        for (int d = 0; d < DD; d++) s += pr[d] * W3[d*(2*DD) + n];
        hid[n] = fmaxf(s, 0.f);
    }
    __syncthreads();
    float s = b4[k];
    #pragma unroll 4
    for (int d = 0; d < 2*DD; d++) s += hid[d] * W4[d*DD + k];
    out_obj[i*DD + k] = fmaxf(s, 0.f);
}

// ---------------- launch ----------------
extern "C" void kernel_launch(void* const* d_in, const int* in_sizes, int n_in,
                              void* d_out, int out_size) {
    const float* obj   = (const float*)d_in[0];
    const float* pred  = (const float*)d_in[1];
    const int*   edges = (const int*)  d_in[2];
    const float* W     = (const float*)d_in[3];
    const float* a     = (const float*)d_in[4];
    const float* W1    = (const float*)d_in[5];
    const float* b1    = (const float*)d_in[6];
    const float* W2    = (const float*)d_in[7];
    const float* b2    = (const float*)d_in[8];
    const float* W3    = (const float*)d_in[9];
    const float* b3    = (const float*)d_in[10];
    const float* W4    = (const float*)d_in[11];
    const float* b4    = (const float*)d_in[12];

    int T = in_sizes[2] / 2;                 // 261632
    float* out_obj = (float*)d_out;          // (512,128) first
    float* out_p   = (float*)d_out + NO*DD;  // (T,128) second

    size_t smem = (size_t)(2 * 128 * LDA + 384) * sizeof(float) + 256 * sizeof(int);
    cudaFuncSetAttribute(k_main, cudaFuncAttributeMaxDynamicSharedMemorySize, (int)smem);

    k_init<<<(NO*DD + 255)/256, 256>>>();
    k_wh<<<NO, DD>>>(obj, W, a);
    k_att<<<NO, DD>>>();
    k_hsho<<<NO, DD>>>(W1, b1);
    k_counts<<<148, 256>>>(edges, T);
    int ntiles = T / TILE_M;                 // 2044
    k_main<<<ntiles, 256, smem>>>(pred, edges, W1, W2, b2, out_p);
    k_tail<<<NO, DD>>>(W3, b3, W4, b4, out_obj);
}